// round 2
// baseline (speedup 1.0000x reference)
#include <cuda_runtime.h>

#define BS 16
#define D 448
#define HW 4096
#define NELEM (BS * D * HW)   // 29,360,128

// ---- scratch (allocation-free: device globals) ----
__device__ float g_WQVS[NELEM];            // W_q @ V_s  per batch  [b][d][h]
__device__ float g_WKVR[NELEM];            // W_k @ V_r  per batch  [b][d][h]
__device__ float g_WVVR[NELEM];            // W_v @ V_r  per batch  [b][d][h]
__device__ float g_scores[2 * BS * D * D]; // [neg][b][d][e], softmaxed in place
__device__ double g_Lsum;

__global__ void k_zero() { g_Lsum = 0.0; }

// ---------------------------------------------------------------------------
// Projection GEMMs: C[b][d][h] = sum_c W[d][c] * V[b][c][h]
// M=448(d) N=4096(h) K=448(c); 48 GEMMs (16 batches x 3 weights)
// ---------------------------------------------------------------------------
__global__ __launch_bounds__(256) void k_proj(const float* __restrict__ Vr,
                                              const float* __restrict__ Vs,
                                              const float* __restrict__ Wq,
                                              const float* __restrict__ Wk,
                                              const float* __restrict__ Wv) {
    const int bz = blockIdx.z;
    const int b = bz / 3, w = bz % 3;
    const float* W = (w == 0) ? Wq : ((w == 1) ? Wk : Wv);
    const float* V = ((w == 0) ? Vs : Vr) + (size_t)b * D * HW;
    float* C = ((w == 0) ? g_WQVS : ((w == 1) ? g_WKVR : g_WVVR)) + (size_t)b * D * HW;

    const int m0 = blockIdx.y * 64;  // d
    const int n0 = blockIdx.x * 64;  // h

    __shared__ float As[16][68];  // As[k][m] (padded: conflict-light writes, aligned f4 reads)
    __shared__ float Bs[16][64];  // Bs[k][n]

    const int t  = threadIdx.x;
    const int tx = t & 15, ty = t >> 4;
    const int a_m = t >> 2, a_k = (t & 3) * 4;   // A loader
    const int b_k = t >> 4, b_n = (t & 15) * 4;  // B loader

    float acc[4][4] = {};

    for (int k0 = 0; k0 < D; k0 += 16) {
        float4 av = *(const float4*)&W[(size_t)(m0 + a_m) * D + k0 + a_k];
        As[a_k + 0][a_m] = av.x;
        As[a_k + 1][a_m] = av.y;
        As[a_k + 2][a_m] = av.z;
        As[a_k + 3][a_m] = av.w;
        *(float4*)&Bs[b_k][b_n] = *(const float4*)&V[(size_t)(k0 + b_k) * HW + n0 + b_n];
        __syncthreads();
#pragma unroll
        for (int k = 0; k < 16; k++) {
            float4 a  = *(const float4*)&As[k][ty * 4];
            float4 bv = *(const float4*)&Bs[k][tx * 4];
            acc[0][0] += a.x * bv.x; acc[0][1] += a.x * bv.y; acc[0][2] += a.x * bv.z; acc[0][3] += a.x * bv.w;
            acc[1][0] += a.y * bv.x; acc[1][1] += a.y * bv.y; acc[1][2] += a.y * bv.z; acc[1][3] += a.y * bv.w;
            acc[2][0] += a.z * bv.x; acc[2][1] += a.z * bv.y; acc[2][2] += a.z * bv.z; acc[2][3] += a.z * bv.w;
            acc[3][0] += a.w * bv.x; acc[3][1] += a.w * bv.y; acc[3][2] += a.w * bv.z; acc[3][3] += a.w * bv.w;
        }
        __syncthreads();
    }
#pragma unroll
    for (int i = 0; i < 4; i++) {
        float4 o = make_float4(acc[i][0], acc[i][1], acc[i][2], acc[i][3]);
        *(float4*)&C[(size_t)(m0 + ty * 4 + i) * HW + n0 + tx * 4] = o;
    }
}

// ---------------------------------------------------------------------------
// Score GEMMs (NT): scores[neg][b][d][e] = (1/sqrt(D)) * sum_h Q[b][d][h] * K[b'][e][h]
// b' = b for pos, (b+1)%16 for neg.  M=N=448, K=4096.
// ---------------------------------------------------------------------------
__global__ __launch_bounds__(256) void k_scores() {
    const int bz = blockIdx.z;
    const int b = bz >> 1, neg = bz & 1;
    const int bk = neg ? ((b + 1) & (BS - 1)) : b;
    const float* A = g_WQVS + (size_t)b * D * HW;
    const float* B = g_WKVR + (size_t)bk * D * HW;
    float* C = g_scores + ((size_t)neg * BS + b) * D * D;

    const int m0 = blockIdx.y * 64;  // d
    const int n0 = blockIdx.x * 64;  // e

    __shared__ float As[16][68];
    __shared__ float Bs[16][68];

    const int t  = threadIdx.x;
    const int tx = t & 15, ty = t >> 4;
    const int a_m = t >> 2, a_k = (t & 3) * 4;

    float acc[4][4] = {};

    for (int k0 = 0; k0 < HW; k0 += 16) {
        float4 av = *(const float4*)&A[(size_t)(m0 + a_m) * HW + k0 + a_k];
        As[a_k + 0][a_m] = av.x;
        As[a_k + 1][a_m] = av.y;
        As[a_k + 2][a_m] = av.z;
        As[a_k + 3][a_m] = av.w;
        float4 bv = *(const float4*)&B[(size_t)(n0 + a_m) * HW + k0 + a_k];
        Bs[a_k + 0][a_m] = bv.x;
        Bs[a_k + 1][a_m] = bv.y;
        Bs[a_k + 2][a_m] = bv.z;
        Bs[a_k + 3][a_m] = bv.w;
        __syncthreads();
#pragma unroll
        for (int k = 0; k < 16; k++) {
            float4 a  = *(const float4*)&As[k][ty * 4];
            float4 bb = *(const float4*)&Bs[k][tx * 4];
            acc[0][0] += a.x * bb.x; acc[0][1] += a.x * bb.y; acc[0][2] += a.x * bb.z; acc[0][3] += a.x * bb.w;
            acc[1][0] += a.y * bb.x; acc[1][1] += a.y * bb.y; acc[1][2] += a.y * bb.z; acc[1][3] += a.y * bb.w;
            acc[2][0] += a.z * bb.x; acc[2][1] += a.z * bb.y; acc[2][2] += a.z * bb.z; acc[2][3] += a.z * bb.w;
            acc[3][0] += a.w * bb.x; acc[3][1] += a.w * bb.y; acc[3][2] += a.w * bb.z; acc[3][3] += a.w * bb.w;
        }
        __syncthreads();
    }
    const float inv_coef = 0.047245559f;  // 1/sqrt(448)
#pragma unroll
    for (int i = 0; i < 4; i++) {
        float4 o = make_float4(acc[i][0] * inv_coef, acc[i][1] * inv_coef,
                               acc[i][2] * inv_coef, acc[i][3] * inv_coef);
        *(float4*)&C[(size_t)(m0 + ty * 4 + i) * D + n0 + tx * 4] = o;
    }
}

// ---------------------------------------------------------------------------
// Softmax in place over last dim (448), one warp per row. 2*16*448 rows.
// ---------------------------------------------------------------------------
__global__ void k_softmax() {
    const int warp = (blockIdx.x * blockDim.x + threadIdx.x) >> 5;
    const int lane = threadIdx.x & 31;
    if (warp >= 2 * BS * D) return;
    float* row = g_scores + (size_t)warp * D;

    float m = -1e30f;
    for (int i = lane; i < D; i += 32) m = fmaxf(m, row[i]);
#pragma unroll
    for (int off = 16; off > 0; off >>= 1) m = fmaxf(m, __shfl_xor_sync(0xffffffffu, m, off));

    float s = 0.f;
    for (int i = lane; i < D; i += 32) {
        float e = __expf(row[i] - m);
        row[i] = e;
        s += e;
    }
#pragma unroll
    for (int off = 16; off > 0; off >>= 1) s += __shfl_xor_sync(0xffffffffu, s, off);
    float inv = 1.0f / s;
    for (int i = lane; i < D; i += 32) row[i] *= inv;
}

// ---------------------------------------------------------------------------
// Apply attention (pos + neg in one pass, sharing the WvVr tile):
//   v_asta = alpha_pos @ WvVr ; v_neg = alpha_neg @ WvVr
//   out = V_s + v_asta ; Lsum += relu(v_neg - v_asta + 12)
// M=448(d) N=4096(h) K=448(e), 16 batches.
// ---------------------------------------------------------------------------
__global__ __launch_bounds__(256) void k_out(const float* __restrict__ Vs,
                                             float* __restrict__ out) {
    const int b = blockIdx.z;
    const float* A1 = g_scores + (size_t)b * D * D;
    const float* A2 = g_scores + (size_t)(BS + b) * D * D;
    const float* Bm = g_WVVR + (size_t)b * D * HW;

    const int m0 = blockIdx.y * 64;  // d
    const int n0 = blockIdx.x * 64;  // h

    __shared__ float As1[16][68];
    __shared__ float As2[16][68];
    __shared__ float Bs[16][64];

    const int t  = threadIdx.x;
    const int tx = t & 15, ty = t >> 4;
    const int a_m = t >> 2, a_k = (t & 3) * 4;
    const int b_k = t >> 4, b_n = (t & 15) * 4;

    float acc1[4][4] = {};
    float acc2[4][4] = {};

    for (int k0 = 0; k0 < D; k0 += 16) {
        float4 av = *(const float4*)&A1[(size_t)(m0 + a_m) * D + k0 + a_k];
        As1[a_k + 0][a_m] = av.x;
        As1[a_k + 1][a_m] = av.y;
        As1[a_k + 2][a_m] = av.z;
        As1[a_k + 3][a_m] = av.w;
        float4 av2 = *(const float4*)&A2[(size_t)(m0 + a_m) * D + k0 + a_k];
        As2[a_k + 0][a_m] = av2.x;
        As2[a_k + 1][a_m] = av2.y;
        As2[a_k + 2][a_m] = av2.z;
        As2[a_k + 3][a_m] = av2.w;
        *(float4*)&Bs[b_k][b_n] = *(const float4*)&Bm[(size_t)(k0 + b_k) * HW + n0 + b_n];
        __syncthreads();
#pragma unroll
        for (int k = 0; k < 16; k++) {
            float4 a1 = *(const float4*)&As1[k][ty * 4];
            float4 a2 = *(const float4*)&As2[k][ty * 4];
            float4 bv = *(const float4*)&Bs[k][tx * 4];
            acc1[0][0] += a1.x * bv.x; acc1[0][1] += a1.x * bv.y; acc1[0][2] += a1.x * bv.z; acc1[0][3] += a1.x * bv.w;
            acc1[1][0] += a1.y * bv.x; acc1[1][1] += a1.y * bv.y; acc1[1][2] += a1.y * bv.z; acc1[1][3] += a1.y * bv.w;
            acc1[2][0] += a1.z * bv.x; acc1[2][1] += a1.z * bv.y; acc1[2][2] += a1.z * bv.z; acc1[2][3] += a1.z * bv.w;
            acc1[3][0] += a1.w * bv.x; acc1[3][1] += a1.w * bv.y; acc1[3][2] += a1.w * bv.z; acc1[3][3] += a1.w * bv.w;
            acc2[0][0] += a2.x * bv.x; acc2[0][1] += a2.x * bv.y; acc2[0][2] += a2.x * bv.z; acc2[0][3] += a2.x * bv.w;
            acc2[1][0] += a2.y * bv.x; acc2[1][1] += a2.y * bv.y; acc2[1][2] += a2.y * bv.z; acc2[1][3] += a2.y * bv.w;
            acc2[2][0] += a2.z * bv.x; acc2[2][1] += a2.z * bv.y; acc2[2][2] += a2.z * bv.z; acc2[2][3] += a2.z * bv.w;
            acc2[3][0] += a2.w * bv.x; acc2[3][1] += a2.w * bv.y; acc2[3][2] += a2.w * bv.z; acc2[3][3] += a2.w * bv.w;
        }
        __syncthreads();
    }

    float lsum = 0.f;
#pragma unroll
    for (int i = 0; i < 4; i++) {
        const size_t base = ((size_t)b * D + m0 + ty * 4 + i) * HW + n0 + tx * 4;
        float4 vs = *(const float4*)&Vs[base];
        float4 o = make_float4(vs.x + acc1[i][0], vs.y + acc1[i][1],
                               vs.z + acc1[i][2], vs.w + acc1[i][3]);
        *(float4*)&out[base] = o;
#pragma unroll
        for (int j = 0; j < 4; j++)
            lsum += fmaxf(acc2[i][j] - acc1[i][j] + 12.0f, 0.0f);
    }

    __shared__ float red[256];
    red[t] = lsum;
    __syncthreads();
#pragma unroll
    for (int s = 128; s > 0; s >>= 1) {
        if (t < s) red[t] += red[t + s];
        __syncthreads();
    }
    if (t == 0) atomicAdd(&g_Lsum, (double)red[0]);
}

__global__ void k_final(float* out, int out_size) {
    if (out_size > NELEM)
        out[NELEM] = (float)(g_Lsum / (double)NELEM);
}

extern "C" void kernel_launch(void* const* d_in, const int* in_sizes, int n_in,
                              void* d_out, int out_size) {
    const float* Vr = (const float*)d_in[0];
    const float* Vs = (const float*)d_in[1];
    const float* Wq = (const float*)d_in[2];
    const float* Wk = (const float*)d_in[3];
    const float* Wv = (const float*)d_in[4];
    float* out = (float*)d_out;

    k_zero<<<1, 1>>>();
    k_proj<<<dim3(HW / 64, D / 64, BS * 3), 256>>>(Vr, Vs, Wq, Wk, Wv);
    k_scores<<<dim3(D / 64, D / 64, BS * 2), 256>>>();
    {
        int warps = 2 * BS * D;
        int threads = warps * 32;
        k_softmax<<<(threads + 255) / 256, 256>>>();
    }
    k_out<<<dim3(HW / 64, D / 64, BS), 256>>>(Vs, out);
    k_final<<<1, 1>>>(out, out_size);
}